// round 2
// baseline (speedup 1.0000x reference)
#include <cuda_runtime.h>
#include <cuda_bf16.h>

#define NN 262144
#define BB 4096
#define GG 8
#define DD 7
#define HH 64
#define NEGV -1000000000.0f

// segment starts scratch (device global: allocation-free)
__device__ int g_starts[BB + 1];

__global__ void seg_starts_kernel(const int* __restrict__ batch) {
    int i = blockIdx.x * blockDim.x + threadIdx.x;
    if (i >= NN) return;
    int cur = batch[i];
    int prev = (i == 0) ? -1 : batch[i - 1];
    for (int b = prev + 1; b <= cur; ++b) g_starts[b] = i;
    if (i == NN - 1) {
        for (int b = cur + 1; b <= BB; ++b) g_starts[b] = NN;
    }
}

// ---- packed f32x2 helpers ----
__device__ __forceinline__ unsigned long long pk2(float a, float b) {
    unsigned long long r;
    asm("mov.b64 %0, {%1, %2};" : "=l"(r) : "f"(a), "f"(b));
    return r;
}
__device__ __forceinline__ void upk2(unsigned long long v, float& a, float& b) {
    asm("mov.b64 {%0, %1}, %2;" : "=f"(a), "=f"(b) : "l"(v));
}
__device__ __forceinline__ unsigned long long fma2(unsigned long long a,
                                                   unsigned long long b,
                                                   unsigned long long c) {
    unsigned long long r;
    asm("fma.rn.f32x2 %0, %1, %2, %3;" : "=l"(r) : "l"(a), "l"(b), "l"(c));
    return r;
}

// Shared layout (floats):
//   [0, 16384)          W1 (256 x 64)
//   [16384, 16832)      W2 (64 x 7)
//   [16840 + w*1280 ..) per-warp scratch: xp pairs (128 x 5 float2), reused as h (8 x 65)
#define SW1_OFF   0
#define SW2_OFF   16384
#define XP_OFF    16840
#define XP_STRIDE 1280
#define SMEM_FLOATS (XP_OFF + 8 * XP_STRIDE)

__global__ void __launch_bounds__(256, 1) maneuver_kernel(
    const float* __restrict__ nf, const float* __restrict__ glob,
    const int* __restrict__ gmask, const int* __restrict__ mm,
    const float* __restrict__ W1, const float* __restrict__ b1,
    const float* __restrict__ W2, const float* __restrict__ b2,
    float* __restrict__ out)
{
    extern __shared__ float sm[];
    float* sW1 = sm + SW1_OFF;
    float* sW2 = sm + SW2_OFF;
    const int tid  = threadIdx.x;
    const int w    = tid >> 5;
    const int lane = tid & 31;
    float* sxp = sm + XP_OFF + w * XP_STRIDE;

    __shared__ int s_nodes[8][8];
    __shared__ int s_cnt[8];

    // stage W1 (64KB) + W2 cooperatively
    {
        const float4* src = (const float4*)W1;
        float4* dst = (float4*)sW1;
        #pragma unroll
        for (int i = 0; i < 16; ++i) dst[tid + 256 * i] = src[tid + 256 * i];
        if (tid < 224) ((float2*)sW2)[tid] = ((const float2*)W2)[tid];
    }
    __syncthreads();

    const int b = blockIdx.x * 8 + w;
    const int s = g_starts[b];
    const int e = g_starts[b + 1];

    // ---- find first <=8 selected nodes in [s, e) ----
    int cnt = 0;
    for (int base = s; base < e && cnt < 8; base += 32) {
        int i = base + lane;
        bool m = (i < e) && (gmask[i] != 0);
        unsigned bal = __ballot_sync(0xffffffffu, m);
        int ns = __popc(bal);
        int want = lane - cnt;   // this lane claims the want-th set bit (0-indexed)
        if (lane < 8 && want >= 0 && want < ns) {
            unsigned mk = bal;
            #pragma unroll
            for (int t = 0; t < 7; ++t) if (t < want) mk &= (mk - 1u);
            s_nodes[w][lane] = base + (__ffs(mk) - 1);
        }
        cnt += ns;
    }
    int V = cnt < 8 ? cnt : 8;
    if (lane == 0) s_cnt[w] = V;
    __syncwarp();

    // ---- per-batch gb = glob[b] @ W1[128:] + b1 (lane owns hidden 2l, 2l+1) ----
    float gl[4];
    #pragma unroll
    for (int i = 0; i < 4; ++i) gl[i] = glob[b * 128 + lane + 32 * i];
    float2 bv = *(const float2*)&b1[2 * lane];
    float g0 = bv.x, g1 = bv.y;
    #pragma unroll
    for (int k = 0; k < 128; ++k) {
        float x = __shfl_sync(0xffffffffu, gl[k >> 5], k & 31);
        float2 wv = *(const float2*)&sW1[(128 + k) * 64 + 2 * lane];
        g0 = fmaf(x, wv.x, g0);
        g1 = fmaf(x, wv.y, g1);
    }

    // ---- gather node rows, store transposed as node-pair float2s ----
    #pragma unroll
    for (int np = 0; np < 4; ++np) {
        int nA = 2 * np, nB = 2 * np + 1;
        int iA = (nA < V) ? s_nodes[w][nA] : -1;
        int iB = (nB < V) ? s_nodes[w][nB] : -1;
        float a0[4], a1[4];
        #pragma unroll
        for (int i = 0; i < 4; ++i) {
            a0[i] = (iA >= 0) ? nf[(size_t)iA * 128 + lane + 32 * i] : 0.f;
            a1[i] = (iB >= 0) ? nf[(size_t)iB * 128 + lane + 32 * i] : 0.f;
        }
        #pragma unroll
        for (int i = 0; i < 4; ++i) {
            int k = lane + 32 * i;
            *(float2*)&sxp[k * 10 + 2 * np] = make_float2(a0[i], a1[i]);
        }
    }
    __syncwarp();

    // ---- layer 1 mainloop: 8 nodes x 2 hidden per lane, f32x2 packed ----
    unsigned long long acc0[4], acc1[4];
    #pragma unroll
    for (int np = 0; np < 4; ++np) {
        acc0[np] = pk2(g0, g0);
        acc1[np] = pk2(g1, g1);
    }
    #pragma unroll 4
    for (int k = 0; k < 128; ++k) {
        float2 wv = *(const float2*)&sW1[k * 64 + 2 * lane];
        unsigned long long ww0 = pk2(wv.x, wv.x);
        unsigned long long ww1 = pk2(wv.y, wv.y);
        #pragma unroll
        for (int np = 0; np < 4; ++np) {
            unsigned long long xx = *(const unsigned long long*)&sxp[k * 10 + 2 * np];
            acc0[np] = fma2(xx, ww0, acc0[np]);
            acc1[np] = fma2(xx, ww1, acc1[np]);
        }
    }

    // ---- relu, stash h into shared (reuse sxp): layout h[n*65 + j] ----
    __syncwarp();
    #pragma unroll
    for (int np = 0; np < 4; ++np) {
        float hx0, hy0, hx1, hy1;
        upk2(acc0[np], hx0, hy0);   // j = 2l : node 2np (x), node 2np+1 (y)
        upk2(acc1[np], hx1, hy1);   // j = 2l+1
        sxp[(2 * np) * 65 + 2 * lane]         = fmaxf(hx0, 0.f);
        sxp[(2 * np) * 65 + 2 * lane + 1]     = fmaxf(hx1, 0.f);
        sxp[(2 * np + 1) * 65 + 2 * lane]     = fmaxf(hy0, 0.f);
        sxp[(2 * np + 1) * 65 + 2 * lane + 1] = fmaxf(hy1, 0.f);
    }
    __syncwarp();

    // ---- layer 2 + mask + store: lane owns output idx = g*7 + d ----
    int Vv = s_cnt[w];
    #pragma unroll
    for (int p = 0; p < 2; ++p) {
        int idx = p * 32 + lane;
        if (idx < 56) {
            int n = idx / 7, d = idx - n * 7;
            float val = NEGV;
            if (n < Vv && mm[b * 56 + idx] != 0) {
                float sum = b2[d];
                #pragma unroll
                for (int j = 0; j < 64; ++j)
                    sum = fmaf(sxp[n * 65 + j], sW2[j * 7 + d], sum);
                val = sum;
            }
            out[b * 56 + idx] = val;
        }
    }
}

extern "C" void kernel_launch(void* const* d_in, const int* in_sizes, int n_in,
                              void* d_out, int out_size) {
    const float* nf    = (const float*)d_in[0];
    const float* glob  = (const float*)d_in[1];
    const int*   gmask = (const int*)d_in[2];
    const int*   batch = (const int*)d_in[3];
    const int*   mm    = (const int*)d_in[4];
    const float* W1    = (const float*)d_in[5];
    const float* b1    = (const float*)d_in[6];
    const float* W2    = (const float*)d_in[7];
    const float* b2    = (const float*)d_in[8];
    float*       out   = (float*)d_out;

    seg_starts_kernel<<<NN / 256, 256>>>(batch);

    size_t smem = (size_t)SMEM_FLOATS * sizeof(float);
    cudaFuncSetAttribute(maneuver_kernel,
                         cudaFuncAttributeMaxDynamicSharedMemorySize, (int)smem);
    maneuver_kernel<<<BB / 8, 256, smem>>>(nf, glob, gmask, mm, W1, b1, W2, b2, out);
}

// round 4
// speedup vs baseline: 1.1612x; 1.1612x over previous
#include <cuda_runtime.h>
#include <cuda_bf16.h>

#define NN 262144
#define BB 4096
#define NEGV -1000000000.0f

__device__ int g_starts[BB + 1];

__global__ void seg_starts_kernel(const int* __restrict__ batch) {
    int i = blockIdx.x * blockDim.x + threadIdx.x;
    if (i >= NN) return;
    int cur = batch[i];
    int prev = (i == 0) ? -1 : batch[i - 1];
    for (int b = prev + 1; b <= cur; ++b) g_starts[b] = i;
    if (i == NN - 1) {
        for (int b = cur + 1; b <= BB; ++b) g_starts[b] = NN;
    }
}

// ---- packed f32x2 helpers ----
__device__ __forceinline__ unsigned long long pk2(float a, float b) {
    unsigned long long r;
    asm("mov.b64 %0, {%1, %2};" : "=l"(r) : "f"(a), "f"(b));
    return r;
}
__device__ __forceinline__ void upk2(unsigned long long v, float& a, float& b) {
    asm("mov.b64 {%0, %1}, %2;" : "=f"(a), "=f"(b) : "l"(v));
}
__device__ __forceinline__ unsigned long long fma2(unsigned long long a,
                                                   unsigned long long b,
                                                   unsigned long long c) {
    unsigned long long r;
    asm("fma.rn.f32x2 %0, %1, %2, %3;" : "=l"(r) : "l"(a), "l"(b), "l"(c));
    return r;
}

// Shared layout (floats):
//   [0, 16384)    W1 (256 x 64)
//   [16384,16832) W2 (64 x 7)
//   [16848 + w*1024) per-warp xp: k-major, 8 floats per k (4 node-pairs),
//                    reused post-mainloop as h (8 nodes x stride 68)
#define SW1_OFF   0
#define SW2_OFF   16384
#define XP_OFF    16848
#define XP_STRIDE 1024
#define SMEM_FLOATS (XP_OFF + 8 * XP_STRIDE)

__global__ void __launch_bounds__(256, 2) maneuver_kernel(
    const float* __restrict__ nf, const float* __restrict__ glob,
    const int* __restrict__ gmask, const int* __restrict__ mm,
    const float* __restrict__ W1, const float* __restrict__ b1,
    const float* __restrict__ W2, const float* __restrict__ b2,
    float* __restrict__ out)
{
    extern __shared__ float sm[];
    float* sW1 = sm + SW1_OFF;
    float* sW2 = sm + SW2_OFF;
    const int tid  = threadIdx.x;
    const int w    = tid >> 5;
    const int lane = tid & 31;
    float* sxp = sm + XP_OFF + w * XP_STRIDE;

    __shared__ int s_nodes[8][8];
    __shared__ int s_cnt[8];

    // stage W1 (64KB) + W2 cooperatively
    {
        const float4* src = (const float4*)W1;
        float4* dst = (float4*)sW1;
        #pragma unroll
        for (int i = 0; i < 16; ++i) dst[tid + 256 * i] = src[tid + 256 * i];
        if (tid < 224) ((float2*)sW2)[tid] = ((const float2*)W2)[tid];
    }

    const int b = blockIdx.x * 8 + w;
    const int s = g_starts[b];
    const int e = g_starts[b + 1];

    // ---- find first <=8 selected nodes in [s, e) ----
    int cnt = 0;
    for (int base = s; base < e && cnt < 8; base += 32) {
        int i = base + lane;
        bool m = (i < e) && (gmask[i] != 0);
        unsigned bal = __ballot_sync(0xffffffffu, m);
        int ns = __popc(bal);
        int want = lane - cnt;   // this lane claims the want-th set bit
        if (lane < 8 && want >= 0 && want < ns) {
            unsigned mk = bal;
            #pragma unroll
            for (int t = 0; t < 7; ++t) if (t < want) mk &= (mk - 1u);
            s_nodes[w][lane] = base + (__ffs(mk) - 1);
        }
        cnt += ns;
    }
    int V = cnt < 8 ? cnt : 8;
    if (lane == 0) s_cnt[w] = V;
    __syncwarp();

    // ---- issue node-feature gathers EARLY (hide DRAM latency under gb loop) ----
    float a[8][4];
    int nidx[8];
    #pragma unroll
    for (int n = 0; n < 8; ++n) nidx[n] = (n < V) ? s_nodes[w][n] : -1;
    #pragma unroll
    for (int n = 0; n < 8; ++n) {
        #pragma unroll
        for (int i = 0; i < 4; ++i)
            a[n][i] = (nidx[n] >= 0) ? __ldg(&nf[(size_t)nidx[n] * 128 + lane + 32 * i]) : 0.f;
    }

    // ---- per-batch gb = glob[b] @ W1[128:] + b1 (lane owns hidden 2l, 2l+1) ----
    float gl[4];
    #pragma unroll
    for (int i = 0; i < 4; ++i) gl[i] = glob[b * 128 + lane + 32 * i];
    __syncthreads();   // W1 staged (also covers s_nodes)
    float2 bv = *(const float2*)&b1[2 * lane];
    float g0 = bv.x, g1 = bv.y;
    #pragma unroll 8
    for (int k = 0; k < 128; ++k) {
        float x = __shfl_sync(0xffffffffu, gl[k >> 5], k & 31);
        float2 wv = *(const float2*)&sW1[(128 + k) * 64 + 2 * lane];
        g0 = fmaf(x, wv.x, g0);
        g1 = fmaf(x, wv.y, g1);
    }

    // ---- store gathered rows transposed: per k, 4 node-pair float2s contiguous ----
    #pragma unroll
    for (int i = 0; i < 4; ++i) {
        int k = lane + 32 * i;
        #pragma unroll
        for (int np = 0; np < 4; ++np)
            *(float2*)&sxp[k * 8 + 2 * np] = make_float2(a[2 * np][i], a[2 * np + 1][i]);
    }
    __syncwarp();

    // ---- layer 1 mainloop: 8 nodes x 2 hidden per lane, f32x2 packed ----
    unsigned long long acc0[4], acc1[4];
    #pragma unroll
    for (int np = 0; np < 4; ++np) {
        acc0[np] = pk2(g0, g0);
        acc1[np] = pk2(g1, g1);
    }
    #pragma unroll 4
    for (int k = 0; k < 128; ++k) {
        float2 wv = *(const float2*)&sW1[k * 64 + 2 * lane];
        unsigned long long ww0 = pk2(wv.x, wv.x);
        unsigned long long ww1 = pk2(wv.y, wv.y);
        ulonglong2 xA = *(const ulonglong2*)&sxp[k * 8];       // pairs 0,1
        ulonglong2 xB = *(const ulonglong2*)&sxp[k * 8 + 4];   // pairs 2,3
        acc0[0] = fma2(xA.x, ww0, acc0[0]);
        acc1[0] = fma2(xA.x, ww1, acc1[0]);
        acc0[1] = fma2(xA.y, ww0, acc0[1]);
        acc1[1] = fma2(xA.y, ww1, acc1[1]);
        acc0[2] = fma2(xB.x, ww0, acc0[2]);
        acc1[2] = fma2(xB.x, ww1, acc1[2]);
        acc0[3] = fma2(xB.y, ww0, acc0[3]);
        acc1[3] = fma2(xB.y, ww1, acc1[3]);
    }

    // ---- relu, stash h into shared (reuse sxp): layout h[n*68 + j] ----
    __syncwarp();
    #pragma unroll
    for (int np = 0; np < 4; ++np) {
        float hx0, hy0, hx1, hy1;
        upk2(acc0[np], hx0, hy0);   // j = 2l : node 2np (x), node 2np+1 (y)
        upk2(acc1[np], hx1, hy1);   // j = 2l+1
        sxp[(2 * np) * 68 + 2 * lane]         = fmaxf(hx0, 0.f);
        sxp[(2 * np) * 68 + 2 * lane + 1]     = fmaxf(hx1, 0.f);
        sxp[(2 * np + 1) * 68 + 2 * lane]     = fmaxf(hy0, 0.f);
        sxp[(2 * np + 1) * 68 + 2 * lane + 1] = fmaxf(hy1, 0.f);
    }
    __syncwarp();

    // ---- layer 2 + mask + store: lane owns output idx = g*7 + d ----
    int Vv = s_cnt[w];
    #pragma unroll
    for (int p = 0; p < 2; ++p) {
        int idx = p * 32 + lane;
        if (idx < 56) {
            int n = idx / 7, d = idx - n * 7;
            float val = NEGV;
            if (n < Vv && mm[b * 56 + idx] != 0) {
                float sum = b2[d];
                #pragma unroll
                for (int j = 0; j < 64; ++j)
                    sum = fmaf(sxp[n * 68 + j], sW2[j * 7 + d], sum);
                val = sum;
            }
            out[b * 56 + idx] = val;
        }
    }
}

extern "C" void kernel_launch(void* const* d_in, const int* in_sizes, int n_in,
                              void* d_out, int out_size) {
    const float* nf    = (const float*)d_in[0];
    const float* glob  = (const float*)d_in[1];
    const int*   gmask = (const int*)d_in[2];
    const int*   batch = (const int*)d_in[3];
    const int*   mm    = (const int*)d_in[4];
    const float* W1    = (const float*)d_in[5];
    const float* b1    = (const float*)d_in[6];
    const float* W2    = (const float*)d_in[7];
    const float* b2    = (const float*)d_in[8];
    float*       out   = (float*)d_out;

    seg_starts_kernel<<<NN / 256, 256>>>(batch);

    size_t smem = (size_t)SMEM_FLOATS * sizeof(float);
    cudaFuncSetAttribute(maneuver_kernel,
                         cudaFuncAttributeMaxDynamicSharedMemorySize, (int)smem);
    maneuver_kernel<<<BB / 8, 256, smem>>>(nf, glob, gmask, mm, W1, b1, W2, b2, out);
}

// round 6
// speedup vs baseline: 1.1623x; 1.0009x over previous
#include <cuda_runtime.h>
#include <cuda_bf16.h>

#define NN 262144
#define BB 4096
#define NEGV -1000000000.0f

__device__ int g_starts[BB + 1];
__device__ float g_gb[BB * 64];   // precomputed glob@W1b + b1

__global__ void seg_starts_kernel(const int* __restrict__ batch) {
    int i = blockIdx.x * blockDim.x + threadIdx.x;
    if (i >= NN) return;
    int cur = batch[i];
    int prev = (i == 0) ? -1 : batch[i - 1];
    for (int b = prev + 1; b <= cur; ++b) g_starts[b] = i;
    if (i == NN - 1) {
        for (int b = cur + 1; b <= BB; ++b) g_starts[b] = NN;
    }
}

// gb[b][j] = glob[b] @ W1[128:][:,j] + b1[j]   (warp per batch, lane owns j=2l,2l+1)
__global__ void __launch_bounds__(256) gb_kernel(
    const float* __restrict__ glob, const float* __restrict__ W1,
    const float* __restrict__ b1)
{
    __shared__ float sW1b[8192];   // W1 rows 128..255 (32KB)
    const int tid = threadIdx.x, w = tid >> 5, lane = tid & 31;
    {
        const float4* src = (const float4*)(W1 + 128 * 64);
        float4* dst = (float4*)sW1b;
        #pragma unroll
        for (int i = 0; i < 8; ++i) dst[tid + 256 * i] = src[tid + 256 * i];
    }
    const int b = blockIdx.x * 8 + w;
    float gl[4];
    #pragma unroll
    for (int i = 0; i < 4; ++i) gl[i] = glob[b * 128 + lane + 32 * i];
    float2 bv = *(const float2*)&b1[2 * lane];
    float g0 = bv.x, g1 = bv.y;
    __syncthreads();
    #pragma unroll 8
    for (int k = 0; k < 128; ++k) {
        float x = __shfl_sync(0xffffffffu, gl[k >> 5], k & 31);
        float2 wv = *(const float2*)&sW1b[k * 64 + 2 * lane];
        g0 = fmaf(x, wv.x, g0);
        g1 = fmaf(x, wv.y, g1);
    }
    *(float2*)&g_gb[b * 64 + 2 * lane] = make_float2(g0, g1);
}

// ---- packed f32x2 helpers ----
__device__ __forceinline__ unsigned long long pk2(float a, float b) {
    unsigned long long r;
    asm("mov.b64 %0, {%1, %2};" : "=l"(r) : "f"(a), "f"(b));
    return r;
}
__device__ __forceinline__ void upk2(unsigned long long v, float& a, float& b) {
    asm("mov.b64 {%0, %1}, %2;" : "=f"(a), "=f"(b) : "l"(v));
}
__device__ __forceinline__ unsigned long long fma2(unsigned long long a,
                                                   unsigned long long b,
                                                   unsigned long long c) {
    unsigned long long r;
    asm("fma.rn.f32x2 %0, %1, %2, %3;" : "=l"(r) : "l"(a), "l"(b), "l"(c));
    return r;
}

// Shared layout (floats):
//   [0, 8192)      W1 rows 0..127 (32KB)
//   [8192, 8648)   W2 (64 x 7) + pad
//   [8656 + w*1024) per-warp xp: k-major, 8 floats per k (4 node-pairs),
//                   reused post-mainloop as h (8 nodes x stride 68)
#define SW1_OFF   0
#define SW2_OFF   8192
#define XP_OFF    8656
#define XP_STRIDE 1024
#define SMEM_FLOATS (XP_OFF + 8 * XP_STRIDE)

__global__ void __launch_bounds__(256, 3) maneuver_kernel(
    const float* __restrict__ nf,
    const int* __restrict__ gmask, const int* __restrict__ mm,
    const float* __restrict__ W1,
    const float* __restrict__ W2, const float* __restrict__ b2,
    float* __restrict__ out)
{
    extern __shared__ float sm[];
    float* sW1 = sm + SW1_OFF;
    float* sW2 = sm + SW2_OFF;
    const int tid  = threadIdx.x;
    const int w    = tid >> 5;
    const int lane = tid & 31;
    float* sxp = sm + XP_OFF + w * XP_STRIDE;

    __shared__ int s_cnt[8];

    // stage W1a (32KB) + W2 cooperatively
    {
        const float4* src = (const float4*)W1;
        float4* dst = (float4*)sW1;
        #pragma unroll
        for (int i = 0; i < 8; ++i) dst[tid + 256 * i] = src[tid + 256 * i];
        if (tid < 224) ((float2*)sW2)[tid] = ((const float2*)W2)[tid];
    }

    const int b = blockIdx.x * 8 + w;
    const int s = g_starts[b];
    const int e = g_starts[b + 1];

    // ---- find first <=8 selected nodes in [s, e) ----
    int cnt = 0;
    int my_node = -1;   // lanes 0..7 each own one node index
    for (int base = s; base < e && cnt < 8; base += 32) {
        int i = base + lane;
        bool m = (i < e) && (gmask[i] != 0);
        unsigned bal = __ballot_sync(0xffffffffu, m);
        int ns = __popc(bal);
        int want = lane - cnt;   // this lane claims the want-th set bit
        if (lane < 8 && want >= 0 && want < ns) {
            unsigned mk = bal;
            #pragma unroll
            for (int t = 0; t < 7; ++t) if (t < want) mk &= (mk - 1u);
            my_node = base + (__ffs(mk) - 1);
        }
        cnt += ns;
    }
    int V = cnt < 8 ? cnt : 8;
    if (lane == 0) s_cnt[w] = V;

    // broadcast node indices to all lanes, issue gathers EARLY
    int nidx[8];
    #pragma unroll
    for (int n = 0; n < 8; ++n)
        nidx[n] = __shfl_sync(0xffffffffu, my_node, n);
    float a[8][4];
    #pragma unroll
    for (int n = 0; n < 8; ++n) {
        #pragma unroll
        for (int i = 0; i < 4; ++i)
            a[n][i] = (nidx[n] >= 0) ? nf[(size_t)nidx[n] * 128 + lane + 32 * i] : 0.f;
    }

    // load precomputed gb (lane owns hidden 2l, 2l+1)
    float2 gv = *(const float2*)&g_gb[b * 64 + 2 * lane];

    __syncthreads();   // W1a/W2 staged

    // ---- store gathered rows transposed: per k, 4 node-pair float2s contiguous ----
    #pragma unroll
    for (int i = 0; i < 4; ++i) {
        int k = lane + 32 * i;
        #pragma unroll
        for (int np = 0; np < 4; ++np)
            *(float2*)&sxp[k * 8 + 2 * np] = make_float2(a[2 * np][i], a[2 * np + 1][i]);
    }
    __syncwarp();

    // ---- layer 1 mainloop: 8 nodes x 2 hidden per lane, f32x2 packed ----
    unsigned long long acc0[4], acc1[4];
    #pragma unroll
    for (int np = 0; np < 4; ++np) {
        acc0[np] = pk2(gv.x, gv.x);
        acc1[np] = pk2(gv.y, gv.y);
    }
    #pragma unroll 4
    for (int k = 0; k < 128; ++k) {
        float2 wv = *(const float2*)&sW1[k * 64 + 2 * lane];
        unsigned long long ww0 = pk2(wv.x, wv.x);
        unsigned long long ww1 = pk2(wv.y, wv.y);
        ulonglong2 xA = *(const ulonglong2*)&sxp[k * 8];       // pairs 0,1
        ulonglong2 xB = *(const ulonglong2*)&sxp[k * 8 + 4];   // pairs 2,3
        acc0[0] = fma2(xA.x, ww0, acc0[0]);
        acc1[0] = fma2(xA.x, ww1, acc1[0]);
        acc0[1] = fma2(xA.y, ww0, acc0[1]);
        acc1[1] = fma2(xA.y, ww1, acc1[1]);
        acc0[2] = fma2(xB.x, ww0, acc0[2]);
        acc1[2] = fma2(xB.x, ww1, acc1[2]);
        acc0[3] = fma2(xB.y, ww0, acc0[3]);
        acc1[3] = fma2(xB.y, ww1, acc1[3]);
    }

    // ---- relu, stash h into shared (reuse sxp): layout h[n*68 + j] ----
    __syncwarp();
    #pragma unroll
    for (int np = 0; np < 4; ++np) {
        float hx0, hy0, hx1, hy1;
        upk2(acc0[np], hx0, hy0);   // j = 2l : node 2np (x), node 2np+1 (y)
        upk2(acc1[np], hx1, hy1);   // j = 2l+1
        sxp[(2 * np) * 68 + 2 * lane]         = fmaxf(hx0, 0.f);
        sxp[(2 * np) * 68 + 2 * lane + 1]     = fmaxf(hx1, 0.f);
        sxp[(2 * np + 1) * 68 + 2 * lane]     = fmaxf(hy0, 0.f);
        sxp[(2 * np + 1) * 68 + 2 * lane + 1] = fmaxf(hy1, 0.f);
    }
    __syncwarp();

    // ---- layer 2 + mask + store: lane owns output idx = g*7 + d ----
    int Vv = s_cnt[w];
    #pragma unroll
    for (int p = 0; p < 2; ++p) {
        int idx = p * 32 + lane;
        if (idx < 56) {
            int n = idx / 7, d = idx - n * 7;
            float val = NEGV;
            if (n < Vv && mm[b * 56 + idx] != 0) {
                float sum = b2[d];
                #pragma unroll
                for (int j = 0; j < 64; ++j)
                    sum = fmaf(sxp[n * 68 + j], sW2[j * 7 + d], sum);
                val = sum;
            }
            out[b * 56 + idx] = val;
        }
    }
}

extern "C" void kernel_launch(void* const* d_in, const int* in_sizes, int n_in,
                              void* d_out, int out_size) {
    const float* nf    = (const float*)d_in[0];
    const float* glob  = (const float*)d_in[1];
    const int*   gmask = (const int*)d_in[2];
    const int*   batch = (const int*)d_in[3];
    const int*   mm    = (const int*)d_in[4];
    const float* W1    = (const float*)d_in[5];
    const float* b1    = (const float*)d_in[6];
    const float* W2    = (const float*)d_in[7];
    const float* b2    = (const float*)d_in[8];
    float*       out   = (float*)d_out;

    seg_starts_kernel<<<NN / 256, 256>>>(batch);
    gb_kernel<<<BB / 8, 256>>>(glob, W1, b1);

    size_t smem = (size_t)SMEM_FLOATS * sizeof(float);
    cudaFuncSetAttribute(maneuver_kernel,
                         cudaFuncAttributeMaxDynamicSharedMemorySize, (int)smem);
    maneuver_kernel<<<BB / 8, 256, smem>>>(nf, gmask, mm, W1, W2, b2, out);
}